// round 13
// baseline (speedup 1.0000x reference)
#include <cuda_runtime.h>
#include <cuda_fp16.h>
#include <cstdint>

#define B_  16
#define C_  256
#define N_  1024
#define NG  4
#define GC  64

typedef __half fp16;

// ---- scratch (static device globals) ----
__device__ fp16  g_hT[(size_t)B_ * N_ * C_];   // groupnorm out, [b][n][c]
__device__ fp16  g_q [(size_t)B_ * N_ * C_];   // [b][n][d], pre-scaled by 1/16
__device__ fp16  g_k [(size_t)B_ * N_ * C_];
__device__ fp16  g_vt[(size_t)B_ * C_ * N_];   // V transposed: [b][d][m]
__device__ fp16  g_p [(size_t)B_ * N_ * N_];   // UNNORMALIZED exp(scores), fp16
__device__ fp16  g_wq[C_ * C_];
__device__ fp16  g_wk[C_ * C_];
__device__ fp16  g_wv[C_ * C_];
__device__ float g_red[B_ * NG][8][2];         // groupnorm partial sums
__device__ float g_rowsum[B_ * N_];            // softmax row sums (atomic)

// ---------------------------------------------------------------------------
// helpers (family-safe PTX: ldmatrix / mma.sync / cp.async)
// ---------------------------------------------------------------------------
__device__ __forceinline__ uint32_t smem_u32(const void* p) {
    return (uint32_t)__cvta_generic_to_shared(p);
}
__device__ __forceinline__ void ldsm4(uint32_t* r, uint32_t addr) {
    asm volatile("ldmatrix.sync.aligned.m8n8.x4.shared.b16 {%0,%1,%2,%3}, [%4];"
                 : "=r"(r[0]), "=r"(r[1]), "=r"(r[2]), "=r"(r[3]) : "r"(addr));
}
__device__ __forceinline__ void mma16816h(uint32_t* c, const uint32_t* a, const uint32_t* b) {
    asm volatile(
        "mma.sync.aligned.m16n8k16.row.col.f16.f16.f16.f16 "
        "{%0,%1}, {%2,%3,%4,%5}, {%6,%7}, {%0,%1};"
        : "+r"(c[0]), "+r"(c[1])
        : "r"(a[0]), "r"(a[1]), "r"(a[2]), "r"(a[3]), "r"(b[0]), "r"(b[1]));
}
__device__ __forceinline__ void cp16(uint32_t dst, const void* src) {
    asm volatile("cp.async.cg.shared.global [%0], [%1], 16;" :: "r"(dst), "l"(src));
}
__device__ __forceinline__ void cp_commit() { asm volatile("cp.async.commit_group;" ::: "memory"); }
__device__ __forceinline__ void cp_wait1()  { asm volatile("cp.async.wait_group 1;" ::: "memory"); }

__device__ __forceinline__ float2 h2f2(uint32_t u) {
    return __half22float2(*reinterpret_cast<__half2*>(&u));
}
__device__ __forceinline__ uint32_t f2h2(float a, float b) {
    __half2 h = __floats2half2_rn(a, b);
    return *reinterpret_cast<uint32_t*>(&h);
}

#define KT      32
#define STRIDE  40
#define TILE_B  (128 * STRIDE * 2)      // 10240 B per operand tile
#define STG_B   (2 * TILE_B)            // 20480 B per stage (A+B)
#define NSTAGE  2
#define GEMM_SMEM (NSTAGE * STG_B)      // 40960 B -> 4 CTAs/SM by smem

// ---------------------------------------------------------------------------
// 2-stage 128x128 GEMM: acc += A[128,K] * B[128,K]^T (fp16 -> fp16 acc)
// 256 threads, warp grid 4(m) x 2(n).
// Order per tile: issue copy(t+1) FIRST (prev iter's trailing sync guarantees
// that buffer is drained), then wait1 (pending={t,t+1} -> t retired), compute.
// ---------------------------------------------------------------------------
__device__ __forceinline__ void copy_tile(const fp16* A, int lda, const fp16* B, int ldb,
                                          uint32_t sA, uint32_t sB, int k0, int tid) {
    #pragma unroll
    for (int c = 0; c < 2; c++) {
        int id = tid + 256 * c;
        int row = id >> 2, col = (id & 3) * 8;
        uint32_t off = (uint32_t)(row * STRIDE + col) * 2;
        cp16(sA + off, A + (size_t)row * lda + k0 + col);
        cp16(sB + off, B + (size_t)row * ldb + k0 + col);
    }
    cp_commit();
}

__device__ __forceinline__ void gemm_ms(const fp16* A, int lda, const fp16* B, int ldb,
                                        int T, char* smem, uint32_t acc[2][8][2], int tid) {
    int lane = tid & 31, wid = tid >> 5;
    int wm = wid & 3, wn = wid >> 2;
    uint32_t base = smem_u32(smem);

    copy_tile(A, lda, B, ldb, base, base + TILE_B, 0, tid);

    int ar = lane & 15, ak = (lane >> 4) * 8;
    for (int t = 0; t < T; t++) {
        int nxt = t + 1;
        if (nxt < T) {
            uint32_t sb = base + (nxt & 1) * STG_B;
            copy_tile(A, lda, B, ldb, sb, sb + TILE_B, nxt * KT, tid);
        } else {
            cp_commit();         // dummy group so wait1 retires the real last tile
        }
        cp_wait1();              // pending = {t, t+1} -> tile t resident
        __syncthreads();

        uint32_t aB = base + (t & 1) * STG_B;
        uint32_t bB = aB + TILE_B;
        #pragma unroll
        for (int kk = 0; kk < 2; kk++) {
            uint32_t af[2][4];
            #pragma unroll
            for (int mt = 0; mt < 2; mt++)
                ldsm4(af[mt], aB + (uint32_t)((wm * 32 + mt * 16 + ar) * STRIDE + kk * 16 + ak) * 2);
            #pragma unroll
            for (int np = 0; np < 4; np++) {
                uint32_t r[4];
                ldsm4(r, bB + (uint32_t)((wn * 64 + np * 16 + ar) * STRIDE + kk * 16 + ak) * 2);
                uint32_t b0[2] = {r[0], r[2]};
                uint32_t b1[2] = {r[1], r[3]};
                #pragma unroll
                for (int mt = 0; mt < 2; mt++) {
                    mma16816h(acc[mt][np * 2],     af[mt], b0);
                    mma16816h(acc[mt][np * 2 + 1], af[mt], b1);
                }
            }
        }
        __syncthreads();   // buffer t drained before copy at iter t+1 overwrites it
    }
}

// ---------------------------------------------------------------------------
// 128x64 GEMM (pv): 3-stage, warp tile 32x32  (unchanged from R11 — passed)
// ---------------------------------------------------------------------------
#define TILE_B64  (64 * STRIDE * 2)          // 5120 B
#define STG_B64   (TILE_B + TILE_B64)        // 15360 B per stage
#define NST64     3
#define GEMM_SMEM64 (NST64 * STG_B64)        // 46080 B -> 4 CTAs/SM

__device__ __forceinline__ void copy_tile64(const fp16* A, int lda, const fp16* B, int ldb,
                                            uint32_t sA, uint32_t sB, int k0, int tid) {
    #pragma unroll
    for (int c = 0; c < 2; c++) {
        int id = tid + 256 * c;
        int row = id >> 2, col = (id & 3) * 8;
        cp16(sA + (uint32_t)(row * STRIDE + col) * 2, A + (size_t)row * lda + k0 + col);
    }
    {
        int row = tid >> 2, col = (tid & 3) * 8;   // 256 chunks = 64 rows
        cp16(sB + (uint32_t)(row * STRIDE + col) * 2, B + (size_t)row * ldb + k0 + col);
    }
    cp_commit();
}

__device__ __forceinline__ void gemm_ms64(const fp16* A, int lda, const fp16* B, int ldb,
                                          int T, char* smem, uint32_t acc[2][4][2], int tid) {
    int lane = tid & 31, wid = tid >> 5;
    int wm = wid & 3, wn = wid >> 2;
    uint32_t base = smem_u32(smem);

    #pragma unroll
    for (int s = 0; s < NST64 - 1; s++)
        copy_tile64(A, lda, B, ldb, base + s * STG_B64, base + s * STG_B64 + TILE_B, s * KT, tid);

    int ar = lane & 15, ak = (lane >> 4) * 8;
    for (int t = 0; t < T; t++) {
        cp_wait1();
        __syncthreads();
        int nxt = t + NST64 - 1;
        if (nxt < T) {
            uint32_t sb = base + (nxt % NST64) * STG_B64;
            copy_tile64(A, lda, B, ldb, sb, sb + TILE_B, nxt * KT, tid);
        } else {
            cp_commit();
        }
        uint32_t aB = base + (t % NST64) * STG_B64;
        uint32_t bB = aB + TILE_B;

        #pragma unroll
        for (int kk = 0; kk < 2; kk++) {
            uint32_t af[2][4];
            #pragma unroll
            for (int mt = 0; mt < 2; mt++)
                ldsm4(af[mt], aB + (uint32_t)((wm * 32 + mt * 16 + ar) * STRIDE + kk * 16 + ak) * 2);
            #pragma unroll
            for (int np = 0; np < 2; np++) {
                uint32_t r[4];
                ldsm4(r, bB + (uint32_t)((wn * 32 + np * 16 + ar) * STRIDE + kk * 16 + ak) * 2);
                uint32_t b0[2] = {r[0], r[2]};
                uint32_t b1[2] = {r[1], r[3]};
                #pragma unroll
                for (int mt = 0; mt < 2; mt++) {
                    mma16816h(acc[mt][np * 2],     af[mt], b0);
                    mma16816h(acc[mt][np * 2 + 1], af[mt], b1);
                }
            }
        }
    }
}

// ---------------------------------------------------------------------------
// 1a. GroupNorm stats (0..511) + weight fp32->fp16 (512..575) + rowsum zero (576..639)
// ---------------------------------------------------------------------------
__global__ __launch_bounds__(256) void gn_stats_kernel(const float* __restrict__ x,
                                                       const float* __restrict__ Wq,
                                                       const float* __restrict__ Wk,
                                                       const float* __restrict__ Wv) {
    int bx = blockIdx.x;
    if (bx >= 576) {
        g_rowsum[(bx - 576) * 256 + threadIdx.x] = 0.f;
        return;
    }
    if (bx >= 512) {
        int i = (bx - 512) * 256 + threadIdx.x;
        float4 a; uint2 u;
        a = reinterpret_cast<const float4*>(Wq)[i];
        u.x = f2h2(a.x, a.y); u.y = f2h2(a.z, a.w);
        reinterpret_cast<uint2*>(g_wq)[i] = u;
        a = reinterpret_cast<const float4*>(Wk)[i];
        u.x = f2h2(a.x, a.y); u.y = f2h2(a.z, a.w);
        reinterpret_cast<uint2*>(g_wk)[i] = u;
        a = reinterpret_cast<const float4*>(Wv)[i];
        u.x = f2h2(a.x, a.y); u.y = f2h2(a.z, a.w);
        reinterpret_cast<uint2*>(g_wv)[i] = u;
        return;
    }
    int s = bx & 7, bg = bx >> 3;
    const float* xp = x + (size_t)bg * GC * N_ + (size_t)s * 8192;
    float sum = 0.f, ss = 0.f;
    #pragma unroll
    for (int i = 0; i < 8; i++) {
        float4 v = reinterpret_cast<const float4*>(xp)[threadIdx.x + i * 256];
        sum += v.x + v.y + v.z + v.w;
        ss  += v.x * v.x + v.y * v.y + v.z * v.z + v.w * v.w;
    }
    __shared__ float sh1[256], sh2[256];
    sh1[threadIdx.x] = sum; sh2[threadIdx.x] = ss;
    __syncthreads();
    for (int o = 128; o > 0; o >>= 1) {
        if (threadIdx.x < o) {
            sh1[threadIdx.x] += sh1[threadIdx.x + o];
            sh2[threadIdx.x] += sh2[threadIdx.x + o];
        }
        __syncthreads();
    }
    if (threadIdx.x == 0) {
        g_red[bg][s][0] = sh1[0];
        g_red[bg][s][1] = sh2[0];
    }
}

// ---------------------------------------------------------------------------
// 1b. GroupNorm apply + transpose: x[b][c][n] -> hT[b][n][c] fp16
// ---------------------------------------------------------------------------
__global__ __launch_bounds__(256) void gn_apply_kernel(const float* __restrict__ x,
                                                       const float* __restrict__ gamma,
                                                       const float* __restrict__ beta) {
    int ns = blockIdx.x, g = blockIdx.y, b = blockIdx.z;
    int bg = b * NG + g;
    float sum = 0.f, ss = 0.f;
    #pragma unroll
    for (int i = 0; i < 8; i++) { sum += g_red[bg][i][0]; ss += g_red[bg][i][1]; }
    const float inv_n = 1.0f / (GC * N_);
    float mean = sum * inv_n;
    float var  = ss * inv_n - mean * mean;
    float rstd = rsqrtf(var + 1e-5f);

    const float* xp = x + (size_t)bg * GC * N_;
    fp16* out = g_hT + (size_t)b * N_ * C_ + g * GC;
    __shared__ float tile[32 * 65];
    int tid = threadIdx.x;
    int nbase = ns * 128;
    for (int n0 = nbase; n0 < nbase + 128; n0 += 32) {
        for (int e = tid; e < GC * 32; e += 256) {
            int c = e >> 5, n = e & 31;
            float v = (xp[(size_t)c * N_ + n0 + n] - mean) * rstd;
            v = v * __ldg(&gamma[g * GC + c]) + __ldg(&beta[g * GC + c]);
            tile[n * 65 + c] = v;
        }
        __syncthreads();
        {
            int n = tid >> 3, u = tid & 7;
            uint32_t pk[4];
            #pragma unroll
            for (int j = 0; j < 4; j++)
                pk[j] = f2h2(tile[n * 65 + u * 8 + 2 * j], tile[n * 65 + u * 8 + 2 * j + 1]);
            *reinterpret_cast<uint4*>(out + (size_t)(n0 + n) * C_ + u * 8) =
                *reinterpret_cast<uint4*>(pk);
        }
        __syncthreads();
    }
}

// ---------------------------------------------------------------------------
// 2. QKV: out = hT @ W^T + b.  mi=0 -> q (x 1/16), mi=1 -> k, mi=2 -> Vt.
// ---------------------------------------------------------------------------
__global__ __launch_bounds__(256, 4) void qkv_kernel(const float* __restrict__ bq,
                                                     const float* __restrict__ bk,
                                                     const float* __restrict__ bv) {
    extern __shared__ __align__(16) char dsm[];
    int tid = threadIdx.x;
    int mi = blockIdx.z % 3, b = blockIdx.z / 3;
    int n0 = blockIdx.x * 128, m0 = blockIdx.y * 128;
    const fp16* A  = g_hT + (size_t)b * N_ * C_ + (size_t)m0 * C_;
    const fp16* Bm = (mi == 0 ? g_wq : mi == 1 ? g_wk : g_wv) + (size_t)n0 * C_;
    uint32_t acc[2][8][2] = {};
    gemm_ms(A, C_, Bm, C_, C_ / KT, dsm, acc, tid);

    int lane = tid & 31, wid = tid >> 5;
    int wm = wid & 3, wn = wid >> 2;
    int quad = lane >> 2, qt = lane & 3;
    const float* bias = (mi == 0) ? bq : (mi == 1) ? bk : bv;

    if (mi < 2) {
        fp16* out = ((mi == 0) ? g_q : g_k) + (size_t)b * N_ * C_;
        float scale = (mi == 0) ? 0.0625f : 1.0f;
        #pragma unroll
        for (int mt = 0; mt < 2; mt++) {
            int r0 = m0 + wm * 32 + mt * 16 + quad;
            #pragma unroll
            for (int nt = 0; nt < 8; nt++) {
                int d = n0 + wn * 64 + nt * 8 + qt * 2;
                float b0 = __ldg(&bias[d]), b1 = __ldg(&bias[d + 1]);
                float2 c01 = h2f2(acc[mt][nt][0]);
                float2 c23 = h2f2(acc[mt][nt][1]);
                uint32_t h0 = f2h2((c01.x + b0) * scale, (c01.y + b1) * scale);
                uint32_t h1 = f2h2((c23.x + b0) * scale, (c23.y + b1) * scale);
                *reinterpret_cast<uint32_t*>(out + (size_t)r0 * C_ + d) = h0;
                *reinterpret_cast<uint32_t*>(out + (size_t)(r0 + 8) * C_ + d) = h1;
            }
        }
    } else {
        fp16* st = reinterpret_cast<fp16*>(dsm);   // [128 d][stride 136] = 34816 B
        __syncthreads();
        #pragma unroll
        for (int mt = 0; mt < 2; mt++) {
            int ml = wm * 32 + mt * 16 + quad;
            #pragma unroll
            for (int nt = 0; nt < 8; nt++) {
                int dl = wn * 64 + nt * 8 + qt * 2;
                float b0 = __ldg(&bias[n0 + dl]), b1 = __ldg(&bias[n0 + dl + 1]);
                float2 c01 = h2f2(acc[mt][nt][0]);
                float2 c23 = h2f2(acc[mt][nt][1]);
                st[dl * 136 + ml]           = __float2half_rn(c01.x + b0);
                st[(dl + 1) * 136 + ml]     = __float2half_rn(c01.y + b1);
                st[dl * 136 + ml + 8]       = __float2half_rn(c23.x + b0);
                st[(dl + 1) * 136 + ml + 8] = __float2half_rn(c23.y + b1);
            }
        }
        __syncthreads();
        fp16* outv = g_vt + (size_t)b * C_ * N_;
        #pragma unroll
        for (int c = 0; c < 8; c++) {
            int id = tid + 256 * c;
            int d = id >> 4, ch = (id & 15) * 8;
            *reinterpret_cast<uint4*>(outv + (size_t)(n0 + d) * N_ + m0 + ch) =
                *reinterpret_cast<uint4*>(st + d * 136 + ch);
        }
    }
}

// ---------------------------------------------------------------------------
// 3. Scores as plain GEMM + exp epilogue (deferred normalization):
//    P[b][m][n] = exp(q.k), g_rowsum[b][m] += partial sums (atomic).
// ---------------------------------------------------------------------------
__global__ __launch_bounds__(256, 4) void score_kernel() {
    extern __shared__ __align__(16) char dsm[];
    int tid = threadIdx.x;
    int b = blockIdx.z;
    int n0 = blockIdx.x * 128, m0 = blockIdx.y * 128;
    const fp16* A  = g_q + (size_t)b * N_ * C_ + (size_t)m0 * C_;
    const fp16* Bm = g_k + (size_t)b * N_ * C_ + (size_t)n0 * C_;
    uint32_t acc[2][8][2] = {};
    gemm_ms(A, C_, Bm, C_, C_ / KT, dsm, acc, tid);

    int lane = tid & 31, wid = tid >> 5;
    int wm = wid & 3, wn = wid >> 2;
    int quad = lane >> 2, qt = lane & 3;

    fp16* P = g_p + (size_t)b * N_ * N_;
    float* rsum = g_rowsum + (size_t)b * N_;
    #pragma unroll
    for (int mt = 0; mt < 2; mt++) {
        int r0 = m0 + wm * 32 + mt * 16 + quad;
        float rs0 = 0.f, rs1 = 0.f;
        #pragma unroll
        for (int nt = 0; nt < 8; nt++) {
            int cc = n0 + wn * 64 + nt * 8 + qt * 2;
            float2 a01 = h2f2(acc[mt][nt][0]);
            float2 a23 = h2f2(acc[mt][nt][1]);
            float e0 = __expf(a01.x), e1 = __expf(a01.y);
            float e2 = __expf(a23.x), e3 = __expf(a23.y);
            rs0 += e0 + e1;
            rs1 += e2 + e3;
            *reinterpret_cast<uint32_t*>(P + (size_t)r0 * N_ + cc)       = f2h2(e0, e1);
            *reinterpret_cast<uint32_t*>(P + (size_t)(r0 + 8) * N_ + cc) = f2h2(e2, e3);
        }
        rs0 += __shfl_xor_sync(0xffffffffu, rs0, 1);
        rs0 += __shfl_xor_sync(0xffffffffu, rs0, 2);
        rs1 += __shfl_xor_sync(0xffffffffu, rs1, 1);
        rs1 += __shfl_xor_sync(0xffffffffu, rs1, 2);
        if (qt == 0) {
            atomicAdd(&rsum[r0], rs0);
            atomicAdd(&rsum[r0 + 8], rs1);
        }
    }
}

// ---------------------------------------------------------------------------
// 4. PV as O^T, tile 128 channels x 64 tokens (512 CTAs, 4 CTAs/SM):
//    out[b][c][n] = (sum_m Vt[b][c][m] * P[b][n][m]) / rowsum[b][n] + x[b][c][n]
// ---------------------------------------------------------------------------
__global__ __launch_bounds__(256, 4) void pv_kernel(const float* __restrict__ x,
                                                    float* __restrict__ outp) {
    extern __shared__ __align__(16) char dsm[];
    int tid = threadIdx.x;
    int b = blockIdx.z;
    int n0 = blockIdx.x * 64;    // token tile (64)
    int m0 = blockIdx.y * 128;   // channel tile (128)
    const fp16* A  = g_vt + (size_t)b * C_ * N_ + (size_t)m0 * N_;
    const fp16* Bm = g_p  + (size_t)b * N_ * N_ + (size_t)n0 * N_;
    uint32_t acc[2][4][2] = {};
    gemm_ms64(A, N_, Bm, N_, N_ / KT, dsm, acc, tid);

    int lane = tid & 31, wid = tid >> 5;
    int wm = wid & 3, wn = wid >> 2;
    int quad = lane >> 2, qt = lane & 3;
    const float* rsum = g_rowsum + (size_t)b * N_;
    #pragma unroll
    for (int mt = 0; mt < 2; mt++) {
        int cg = m0 + wm * 32 + mt * 16 + quad;
        #pragma unroll
        for (int nt = 0; nt < 4; nt++) {
            int ng = n0 + wn * 32 + nt * 8 + qt * 2;
            float inv0 = 1.0f / __ldg(&rsum[ng]);
            float inv1 = 1.0f / __ldg(&rsum[ng + 1]);
            size_t base = ((size_t)b * C_ + cg) * N_ + ng;
            float2 c01 = h2f2(acc[mt][nt][0]);
            float2 c23 = h2f2(acc[mt][nt][1]);
            float2 xv = *reinterpret_cast<const float2*>(x + base);
            *reinterpret_cast<float2*>(outp + base) =
                make_float2(c01.x * inv0 + xv.x, c01.y * inv1 + xv.y);
            size_t base8 = base + (size_t)8 * N_;
            float2 xv8 = *reinterpret_cast<const float2*>(x + base8);
            *reinterpret_cast<float2*>(outp + base8) =
                make_float2(c23.x * inv0 + xv8.x, c23.y * inv1 + xv8.y);
        }
    }
}

// ---------------------------------------------------------------------------
extern "C" void kernel_launch(void* const* d_in, const int* in_sizes, int n_in,
                              void* d_out, int out_size) {
    const float* x     = (const float*)d_in[0];
    const float* Wq    = (const float*)d_in[1];
    const float* bq    = (const float*)d_in[2];
    const float* Wk    = (const float*)d_in[3];
    const float* bk    = (const float*)d_in[4];
    const float* Wv    = (const float*)d_in[5];
    const float* bv    = (const float*)d_in[6];
    const float* gamma = (const float*)d_in[7];
    const float* beta  = (const float*)d_in[8];
    float* out = (float*)d_out;

    cudaFuncSetAttribute(qkv_kernel, cudaFuncAttributeMaxDynamicSharedMemorySize, GEMM_SMEM);
    cudaFuncSetAttribute(score_kernel, cudaFuncAttributeMaxDynamicSharedMemorySize, GEMM_SMEM);
    cudaFuncSetAttribute(pv_kernel, cudaFuncAttributeMaxDynamicSharedMemorySize, GEMM_SMEM64);

    gn_stats_kernel<<<640, 256>>>(x, Wq, Wk, Wv);
    gn_apply_kernel<<<dim3(8, NG, B_), 256>>>(x, gamma, beta);
    qkv_kernel<<<dim3(2, 8, 3 * B_), 256, GEMM_SMEM>>>(bq, bk, bv);
    score_kernel<<<dim3(8, 8, B_), 256, GEMM_SMEM>>>();
    pv_kernel<<<dim3(16, 2, B_), 256, GEMM_SMEM64>>>(x, out);
}

// round 14
// speedup vs baseline: 1.0145x; 1.0145x over previous
#include <cuda_runtime.h>
#include <cuda_fp16.h>
#include <cstdint>

#define B_  16
#define C_  256
#define N_  1024
#define NG  4
#define GC  64

typedef __half fp16;

// ---- scratch (static device globals) ----
__device__ fp16  g_hT[(size_t)B_ * N_ * C_];   // groupnorm out, [b][n][c]
__device__ fp16  g_q [(size_t)B_ * N_ * C_];   // [b][n][d], pre-scaled by 1/16
__device__ fp16  g_k [(size_t)B_ * N_ * C_];
__device__ fp16  g_vt[(size_t)B_ * C_ * N_];   // V transposed: [b][d][m]
__device__ fp16  g_p [(size_t)B_ * N_ * N_];   // UNNORMALIZED exp(scores), fp16
__device__ fp16  g_wq[C_ * C_];
__device__ fp16  g_wk[C_ * C_];
__device__ fp16  g_wv[C_ * C_];
__device__ float g_red[B_ * NG][8][2];         // groupnorm partial sums
__device__ float g_rowsum[B_ * N_];            // softmax row sums (atomic)

// ---------------------------------------------------------------------------
// helpers (family-safe PTX: ldmatrix / mma.sync / cp.async)
// ---------------------------------------------------------------------------
__device__ __forceinline__ uint32_t smem_u32(const void* p) {
    return (uint32_t)__cvta_generic_to_shared(p);
}
__device__ __forceinline__ void ldsm4(uint32_t* r, uint32_t addr) {
    asm volatile("ldmatrix.sync.aligned.m8n8.x4.shared.b16 {%0,%1,%2,%3}, [%4];"
                 : "=r"(r[0]), "=r"(r[1]), "=r"(r[2]), "=r"(r[3]) : "r"(addr));
}
__device__ __forceinline__ void mma16816h(uint32_t* c, const uint32_t* a, const uint32_t* b) {
    asm volatile(
        "mma.sync.aligned.m16n8k16.row.col.f16.f16.f16.f16 "
        "{%0,%1}, {%2,%3,%4,%5}, {%6,%7}, {%0,%1};"
        : "+r"(c[0]), "+r"(c[1])
        : "r"(a[0]), "r"(a[1]), "r"(a[2]), "r"(a[3]), "r"(b[0]), "r"(b[1]));
}
__device__ __forceinline__ void cp16(uint32_t dst, const void* src) {
    asm volatile("cp.async.cg.shared.global [%0], [%1], 16;" :: "r"(dst), "l"(src));
}
__device__ __forceinline__ void cp_commit() { asm volatile("cp.async.commit_group;" ::: "memory"); }
__device__ __forceinline__ void cp_wait1()  { asm volatile("cp.async.wait_group 1;" ::: "memory"); }

__device__ __forceinline__ float2 h2f2(uint32_t u) {
    return __half22float2(*reinterpret_cast<__half2*>(&u));
}
__device__ __forceinline__ uint32_t f2h2(float a, float b) {
    __half2 h = __floats2half2_rn(a, b);
    return *reinterpret_cast<uint32_t*>(&h);
}

#define KT      32
#define STRIDE  40
#define TILE_B  (128 * STRIDE * 2)      // 10240 B per operand tile
#define STG_B   (2 * TILE_B)            // 20480 B per stage (A+B)
#define NSTAGE  2
#define GEMM_SMEM (NSTAGE * STG_B)      // 40960 B

// ---------------------------------------------------------------------------
// 2-stage 128x128 GEMM: acc += A[128,K] * B[128,K]^T (fp16 -> fp16 acc)
// 256 threads, warp grid 4(m) x 2(n). Fully-unrolled k-loop (LDA/LDB/T are
// template constants -> stage addressing folds to immediates).
// ---------------------------------------------------------------------------
template <int LD>
__device__ __forceinline__ void copy_tile(const fp16* A, const fp16* B,
                                          uint32_t sA, uint32_t sB, int k0, int tid) {
    #pragma unroll
    for (int c = 0; c < 2; c++) {
        int id = tid + 256 * c;
        int row = id >> 2, col = (id & 3) * 8;
        uint32_t off = (uint32_t)(row * STRIDE + col) * 2;
        cp16(sA + off, A + (size_t)row * LD + k0 + col);
        cp16(sB + off, B + (size_t)row * LD + k0 + col);
    }
    cp_commit();
}

template <int T, int LD>
__device__ __forceinline__ void gemm_ms(const fp16* A, const fp16* B,
                                        char* smem, uint32_t acc[2][8][2], int tid) {
    int lane = tid & 31, wid = tid >> 5;
    int wm = wid & 3, wn = wid >> 2;
    uint32_t base = smem_u32(smem);

    copy_tile<LD>(A, B, base, base + TILE_B, 0, tid);

    int ar = lane & 15, ak = (lane >> 4) * 8;
    // precomputed per-warp ldsm base offsets (relative to stage base)
    uint32_t aoff = (uint32_t)((wm * 32 + ar) * STRIDE + ak) * 2;
    uint32_t boff = (uint32_t)((wn * 64 + ar) * STRIDE + ak) * 2 + TILE_B;

    #pragma unroll
    for (int t = 0; t < T; t++) {
        if (t + 1 < T) {
            uint32_t sb = base + ((t + 1) & 1) * STG_B;
            copy_tile<LD>(A, B, sb, sb + TILE_B, (t + 1) * KT, tid);
        } else {
            cp_commit();         // dummy group so wait1 retires the real last tile
        }
        cp_wait1();              // pending = {t, t+1} -> tile t resident
        __syncthreads();

        uint32_t stg = base + (t & 1) * STG_B;
        #pragma unroll
        for (int kk = 0; kk < 2; kk++) {
            uint32_t af[2][4];
            #pragma unroll
            for (int mt = 0; mt < 2; mt++)
                ldsm4(af[mt], stg + aoff + (uint32_t)(mt * 16 * STRIDE + kk * 16) * 2);
            #pragma unroll
            for (int np = 0; np < 4; np++) {
                uint32_t r[4];
                ldsm4(r, stg + boff + (uint32_t)(np * 16 * STRIDE + kk * 16) * 2);
                uint32_t b0[2] = {r[0], r[2]};
                uint32_t b1[2] = {r[1], r[3]};
                #pragma unroll
                for (int mt = 0; mt < 2; mt++) {
                    mma16816h(acc[mt][np * 2],     af[mt], b0);
                    mma16816h(acc[mt][np * 2 + 1], af[mt], b1);
                }
            }
        }
        __syncthreads();   // buffer t drained before copy at iter t+1 overwrites it
    }
}

// ---------------------------------------------------------------------------
// 128x64 GEMM (pv): 3-stage, warp tile 32x32, unroll-4 mainloop
// ---------------------------------------------------------------------------
#define TILE_B64  (64 * STRIDE * 2)          // 5120 B
#define STG_B64   (TILE_B + TILE_B64)        // 15360 B per stage
#define NST64     3
#define GEMM_SMEM64 (NST64 * STG_B64)        // 46080 B -> 4 CTAs/SM

template <int LD>
__device__ __forceinline__ void copy_tile64(const fp16* A, const fp16* B,
                                            uint32_t sA, uint32_t sB, int k0, int tid) {
    #pragma unroll
    for (int c = 0; c < 2; c++) {
        int id = tid + 256 * c;
        int row = id >> 2, col = (id & 3) * 8;
        cp16(sA + (uint32_t)(row * STRIDE + col) * 2, A + (size_t)row * LD + k0 + col);
    }
    {
        int row = tid >> 2, col = (tid & 3) * 8;   // 256 chunks = 64 rows
        cp16(sB + (uint32_t)(row * STRIDE + col) * 2, B + (size_t)row * LD + k0 + col);
    }
    cp_commit();
}

template <int T, int LD>
__device__ __forceinline__ void gemm_ms64(const fp16* A, const fp16* B,
                                          char* smem, uint32_t acc[2][4][2], int tid) {
    int lane = tid & 31, wid = tid >> 5;
    int wm = wid & 3, wn = wid >> 2;
    uint32_t base = smem_u32(smem);

    #pragma unroll
    for (int s = 0; s < NST64 - 1; s++)
        copy_tile64<LD>(A, B, base + s * STG_B64, base + s * STG_B64 + TILE_B, s * KT, tid);

    int ar = lane & 15, ak = (lane >> 4) * 8;
    uint32_t aoff = (uint32_t)((wm * 32 + ar) * STRIDE + ak) * 2;
    uint32_t boff = (uint32_t)((wn * 32 + ar) * STRIDE + ak) * 2 + TILE_B;

    #pragma unroll 4
    for (int t = 0; t < T; t++) {
        cp_wait1();
        __syncthreads();
        int nxt = t + NST64 - 1;
        if (nxt < T) {
            uint32_t sb = base + (nxt % NST64) * STG_B64;
            copy_tile64<LD>(A, B, sb, sb + TILE_B, nxt * KT, tid);
        } else {
            cp_commit();
        }
        uint32_t stg = base + (t % NST64) * STG_B64;

        #pragma unroll
        for (int kk = 0; kk < 2; kk++) {
            uint32_t af[2][4];
            #pragma unroll
            for (int mt = 0; mt < 2; mt++)
                ldsm4(af[mt], stg + aoff + (uint32_t)(mt * 16 * STRIDE + kk * 16) * 2);
            #pragma unroll
            for (int np = 0; np < 2; np++) {
                uint32_t r[4];
                ldsm4(r, stg + boff + (uint32_t)(np * 16 * STRIDE + kk * 16) * 2);
                uint32_t b0[2] = {r[0], r[2]};
                uint32_t b1[2] = {r[1], r[3]};
                #pragma unroll
                for (int mt = 0; mt < 2; mt++) {
                    mma16816h(acc[mt][np * 2],     af[mt], b0);
                    mma16816h(acc[mt][np * 2 + 1], af[mt], b1);
                }
            }
        }
    }
}

// ---------------------------------------------------------------------------
// 1a. GroupNorm stats (0..511) + weight fp32->fp16 (512..575) + rowsum zero (576..639)
// ---------------------------------------------------------------------------
__global__ __launch_bounds__(256) void gn_stats_kernel(const float* __restrict__ x,
                                                       const float* __restrict__ Wq,
                                                       const float* __restrict__ Wk,
                                                       const float* __restrict__ Wv) {
    int bx = blockIdx.x;
    if (bx >= 576) {
        g_rowsum[(bx - 576) * 256 + threadIdx.x] = 0.f;
        return;
    }
    if (bx >= 512) {
        int i = (bx - 512) * 256 + threadIdx.x;
        float4 a; uint2 u;
        a = reinterpret_cast<const float4*>(Wq)[i];
        u.x = f2h2(a.x, a.y); u.y = f2h2(a.z, a.w);
        reinterpret_cast<uint2*>(g_wq)[i] = u;
        a = reinterpret_cast<const float4*>(Wk)[i];
        u.x = f2h2(a.x, a.y); u.y = f2h2(a.z, a.w);
        reinterpret_cast<uint2*>(g_wk)[i] = u;
        a = reinterpret_cast<const float4*>(Wv)[i];
        u.x = f2h2(a.x, a.y); u.y = f2h2(a.z, a.w);
        reinterpret_cast<uint2*>(g_wv)[i] = u;
        return;
    }
    int s = bx & 7, bg = bx >> 3;
    const float* xp = x + (size_t)bg * GC * N_ + (size_t)s * 8192;
    float sum = 0.f, ss = 0.f;
    #pragma unroll
    for (int i = 0; i < 8; i++) {
        float4 v = reinterpret_cast<const float4*>(xp)[threadIdx.x + i * 256];
        sum += v.x + v.y + v.z + v.w;
        ss  += v.x * v.x + v.y * v.y + v.z * v.z + v.w * v.w;
    }
    __shared__ float sh1[256], sh2[256];
    sh1[threadIdx.x] = sum; sh2[threadIdx.x] = ss;
    __syncthreads();
    for (int o = 128; o > 0; o >>= 1) {
        if (threadIdx.x < o) {
            sh1[threadIdx.x] += sh1[threadIdx.x + o];
            sh2[threadIdx.x] += sh2[threadIdx.x + o];
        }
        __syncthreads();
    }
    if (threadIdx.x == 0) {
        g_red[bg][s][0] = sh1[0];
        g_red[bg][s][1] = sh2[0];
    }
}

// ---------------------------------------------------------------------------
// 1b. GroupNorm apply + transpose: x[b][c][n] -> hT[b][n][c] fp16
// ---------------------------------------------------------------------------
__global__ __launch_bounds__(256) void gn_apply_kernel(const float* __restrict__ x,
                                                       const float* __restrict__ gamma,
                                                       const float* __restrict__ beta) {
    int ns = blockIdx.x, g = blockIdx.y, b = blockIdx.z;
    int bg = b * NG + g;
    float sum = 0.f, ss = 0.f;
    #pragma unroll
    for (int i = 0; i < 8; i++) { sum += g_red[bg][i][0]; ss += g_red[bg][i][1]; }
    const float inv_n = 1.0f / (GC * N_);
    float mean = sum * inv_n;
    float var  = ss * inv_n - mean * mean;
    float rstd = rsqrtf(var + 1e-5f);

    const float* xp = x + (size_t)bg * GC * N_;
    fp16* out = g_hT + (size_t)b * N_ * C_ + g * GC;
    __shared__ float tile[32 * 65];
    int tid = threadIdx.x;
    int nbase = ns * 128;
    for (int n0 = nbase; n0 < nbase + 128; n0 += 32) {
        for (int e = tid; e < GC * 32; e += 256) {
            int c = e >> 5, n = e & 31;
            float v = (xp[(size_t)c * N_ + n0 + n] - mean) * rstd;
            v = v * __ldg(&gamma[g * GC + c]) + __ldg(&beta[g * GC + c]);
            tile[n * 65 + c] = v;
        }
        __syncthreads();
        {
            int n = tid >> 3, u = tid & 7;
            uint32_t pk[4];
            #pragma unroll
            for (int j = 0; j < 4; j++)
                pk[j] = f2h2(tile[n * 65 + u * 8 + 2 * j], tile[n * 65 + u * 8 + 2 * j + 1]);
            *reinterpret_cast<uint4*>(out + (size_t)(n0 + n) * C_ + u * 8) =
                *reinterpret_cast<uint4*>(pk);
        }
        __syncthreads();
    }
}

// ---------------------------------------------------------------------------
// 2. QKV: out = hT @ W^T + b.  mi=0 -> q (x 1/16), mi=1 -> k, mi=2 -> Vt.
// ---------------------------------------------------------------------------
__global__ __launch_bounds__(256, 3) void qkv_kernel(const float* __restrict__ bq,
                                                     const float* __restrict__ bk,
                                                     const float* __restrict__ bv) {
    extern __shared__ __align__(16) char dsm[];
    int tid = threadIdx.x;
    int mi = blockIdx.z % 3, b = blockIdx.z / 3;
    int n0 = blockIdx.x * 128, m0 = blockIdx.y * 128;
    const fp16* A  = g_hT + (size_t)b * N_ * C_ + (size_t)m0 * C_;
    const fp16* Bm = (mi == 0 ? g_wq : mi == 1 ? g_wk : g_wv) + (size_t)n0 * C_;
    uint32_t acc[2][8][2] = {};
    gemm_ms<C_ / KT, C_>(A, Bm, dsm, acc, tid);

    int lane = tid & 31, wid = tid >> 5;
    int wm = wid & 3, wn = wid >> 2;
    int quad = lane >> 2, qt = lane & 3;
    const float* bias = (mi == 0) ? bq : (mi == 1) ? bk : bv;

    if (mi < 2) {
        fp16* out = ((mi == 0) ? g_q : g_k) + (size_t)b * N_ * C_;
        float scale = (mi == 0) ? 0.0625f : 1.0f;
        #pragma unroll
        for (int mt = 0; mt < 2; mt++) {
            int r0 = m0 + wm * 32 + mt * 16 + quad;
            #pragma unroll
            for (int nt = 0; nt < 8; nt++) {
                int d = n0 + wn * 64 + nt * 8 + qt * 2;
                float b0 = __ldg(&bias[d]), b1 = __ldg(&bias[d + 1]);
                float2 c01 = h2f2(acc[mt][nt][0]);
                float2 c23 = h2f2(acc[mt][nt][1]);
                uint32_t h0 = f2h2((c01.x + b0) * scale, (c01.y + b1) * scale);
                uint32_t h1 = f2h2((c23.x + b0) * scale, (c23.y + b1) * scale);
                *reinterpret_cast<uint32_t*>(out + (size_t)r0 * C_ + d) = h0;
                *reinterpret_cast<uint32_t*>(out + (size_t)(r0 + 8) * C_ + d) = h1;
            }
        }
    } else {
        fp16* st = reinterpret_cast<fp16*>(dsm);   // [128 d][stride 136] = 34816 B
        __syncthreads();
        #pragma unroll
        for (int mt = 0; mt < 2; mt++) {
            int ml = wm * 32 + mt * 16 + quad;
            #pragma unroll
            for (int nt = 0; nt < 8; nt++) {
                int dl = wn * 64 + nt * 8 + qt * 2;
                float b0 = __ldg(&bias[n0 + dl]), b1 = __ldg(&bias[n0 + dl + 1]);
                float2 c01 = h2f2(acc[mt][nt][0]);
                float2 c23 = h2f2(acc[mt][nt][1]);
                st[dl * 136 + ml]           = __float2half_rn(c01.x + b0);
                st[(dl + 1) * 136 + ml]     = __float2half_rn(c01.y + b1);
                st[dl * 136 + ml + 8]       = __float2half_rn(c23.x + b0);
                st[(dl + 1) * 136 + ml + 8] = __float2half_rn(c23.y + b1);
            }
        }
        __syncthreads();
        fp16* outv = g_vt + (size_t)b * C_ * N_;
        #pragma unroll
        for (int c = 0; c < 8; c++) {
            int id = tid + 256 * c;
            int d = id >> 4, ch = (id & 15) * 8;
            *reinterpret_cast<uint4*>(outv + (size_t)(n0 + d) * N_ + m0 + ch) =
                *reinterpret_cast<uint4*>(st + d * 136 + ch);
        }
    }
}

// ---------------------------------------------------------------------------
// 3. Scores as plain GEMM + exp epilogue (deferred normalization):
//    P[b][m][n] = exp(q.k), g_rowsum[b][m] += partial sums (atomic).
// ---------------------------------------------------------------------------
__global__ __launch_bounds__(256, 3) void score_kernel() {
    extern __shared__ __align__(16) char dsm[];
    int tid = threadIdx.x;
    int b = blockIdx.z;
    int n0 = blockIdx.x * 128, m0 = blockIdx.y * 128;
    const fp16* A  = g_q + (size_t)b * N_ * C_ + (size_t)m0 * C_;
    const fp16* Bm = g_k + (size_t)b * N_ * C_ + (size_t)n0 * C_;
    uint32_t acc[2][8][2] = {};
    gemm_ms<C_ / KT, C_>(A, Bm, dsm, acc, tid);

    int lane = tid & 31, wid = tid >> 5;
    int wm = wid & 3, wn = wid >> 2;
    int quad = lane >> 2, qt = lane & 3;

    fp16* P = g_p + (size_t)b * N_ * N_;
    float* rsum = g_rowsum + (size_t)b * N_;
    #pragma unroll
    for (int mt = 0; mt < 2; mt++) {
        int r0 = m0 + wm * 32 + mt * 16 + quad;
        float rs0 = 0.f, rs1 = 0.f;
        #pragma unroll
        for (int nt = 0; nt < 8; nt++) {
            int cc = n0 + wn * 64 + nt * 8 + qt * 2;
            float2 a01 = h2f2(acc[mt][nt][0]);
            float2 a23 = h2f2(acc[mt][nt][1]);
            float e0 = __expf(a01.x), e1 = __expf(a01.y);
            float e2 = __expf(a23.x), e3 = __expf(a23.y);
            rs0 += e0 + e1;
            rs1 += e2 + e3;
            *reinterpret_cast<uint32_t*>(P + (size_t)r0 * N_ + cc)       = f2h2(e0, e1);
            *reinterpret_cast<uint32_t*>(P + (size_t)(r0 + 8) * N_ + cc) = f2h2(e2, e3);
        }
        rs0 += __shfl_xor_sync(0xffffffffu, rs0, 1);
        rs0 += __shfl_xor_sync(0xffffffffu, rs0, 2);
        rs1 += __shfl_xor_sync(0xffffffffu, rs1, 1);
        rs1 += __shfl_xor_sync(0xffffffffu, rs1, 2);
        if (qt == 0) {
            atomicAdd(&rsum[r0], rs0);
            atomicAdd(&rsum[r0 + 8], rs1);
        }
    }
}

// ---------------------------------------------------------------------------
// 4. PV as O^T, tile 128 channels x 64 tokens (512 CTAs, 4 CTAs/SM):
//    out[b][c][n] = (sum_m Vt[b][c][m] * P[b][n][m]) / rowsum[b][n] + x[b][c][n]
// ---------------------------------------------------------------------------
__global__ __launch_bounds__(256, 4) void pv_kernel(const float* __restrict__ x,
                                                    float* __restrict__ outp) {
    extern __shared__ __align__(16) char dsm[];
    int tid = threadIdx.x;
    int b = blockIdx.z;
    int n0 = blockIdx.x * 64;    // token tile (64)
    int m0 = blockIdx.y * 128;   // channel tile (128)
    const fp16* A  = g_vt + (size_t)b * C_ * N_ + (size_t)m0 * N_;
    const fp16* Bm = g_p  + (size_t)b * N_ * N_ + (size_t)n0 * N_;
    uint32_t acc[2][4][2] = {};
    gemm_ms64<N_ / KT, N_>(A, Bm, dsm, acc, tid);

    int lane = tid & 31, wid = tid >> 5;
    int wm = wid & 3, wn = wid >> 2;
    int quad = lane >> 2, qt = lane & 3;
    const float* rsum = g_rowsum + (size_t)b * N_;
    #pragma unroll
    for (int mt = 0; mt < 2; mt++) {
        int cg = m0 + wm * 32 + mt * 16 + quad;
        #pragma unroll
        for (int nt = 0; nt < 4; nt++) {
            int ng = n0 + wn * 32 + nt * 8 + qt * 2;
            float inv0 = 1.0f / __ldg(&rsum[ng]);
            float inv1 = 1.0f / __ldg(&rsum[ng + 1]);
            size_t base = ((size_t)b * C_ + cg) * N_ + ng;
            float2 c01 = h2f2(acc[mt][nt][0]);
            float2 c23 = h2f2(acc[mt][nt][1]);
            float2 xv = *reinterpret_cast<const float2*>(x + base);
            *reinterpret_cast<float2*>(outp + base) =
                make_float2(c01.x * inv0 + xv.x, c01.y * inv1 + xv.y);
            size_t base8 = base + (size_t)8 * N_;
            float2 xv8 = *reinterpret_cast<const float2*>(x + base8);
            *reinterpret_cast<float2*>(outp + base8) =
                make_float2(c23.x * inv0 + xv8.x, c23.y * inv1 + xv8.y);
        }
    }
}

// ---------------------------------------------------------------------------
extern "C" void kernel_launch(void* const* d_in, const int* in_sizes, int n_in,
                              void* d_out, int out_size) {
    const float* x     = (const float*)d_in[0];
    const float* Wq    = (const float*)d_in[1];
    const float* bq    = (const float*)d_in[2];
    const float* Wk    = (const float*)d_in[3];
    const float* bk    = (const float*)d_in[4];
    const float* Wv    = (const float*)d_in[5];
    const float* bv    = (const float*)d_in[6];
    const float* gamma = (const float*)d_in[7];
    const float* beta  = (const float*)d_in[8];
    float* out = (float*)d_out;

    cudaFuncSetAttribute(qkv_kernel, cudaFuncAttributeMaxDynamicSharedMemorySize, GEMM_SMEM);
    cudaFuncSetAttribute(score_kernel, cudaFuncAttributeMaxDynamicSharedMemorySize, GEMM_SMEM);
    cudaFuncSetAttribute(pv_kernel, cudaFuncAttributeMaxDynamicSharedMemorySize, GEMM_SMEM64);

    gn_stats_kernel<<<640, 256>>>(x, Wq, Wk, Wv);
    gn_apply_kernel<<<dim3(8, NG, B_), 256>>>(x, gamma, beta);
    qkv_kernel<<<dim3(2, 8, 3 * B_), 256, GEMM_SMEM>>>(bq, bk, bv);
    score_kernel<<<dim3(8, 8, B_), 256, GEMM_SMEM>>>();
    pv_kernel<<<dim3(16, 2, B_), 256, GEMM_SMEM64>>>(x, out);
}

// round 15
// speedup vs baseline: 1.0200x; 1.0054x over previous
#include <cuda_runtime.h>
#include <cuda_fp16.h>
#include <cstdint>

#define B_  16
#define C_  256
#define N_  1024
#define NG  4
#define GC  64

typedef __half fp16;

// ---- scratch (static device globals) ----
__device__ fp16  g_hT[(size_t)B_ * N_ * C_];   // groupnorm out, [b][n][c]
__device__ fp16  g_q [(size_t)B_ * N_ * C_];   // [b][n][d], pre-scaled by 1/16
__device__ fp16  g_k [(size_t)B_ * N_ * C_];
__device__ fp16  g_vt[(size_t)B_ * C_ * N_];   // V transposed: [b][d][m]
__device__ fp16  g_p [(size_t)B_ * N_ * N_];   // UNNORMALIZED exp(scores), fp16
__device__ fp16  g_wq[C_ * C_];
__device__ fp16  g_wk[C_ * C_];
__device__ fp16  g_wv[C_ * C_];
__device__ float g_red[B_ * NG][8][2];         // groupnorm partial sums
__device__ float g_rowsum[B_ * N_];            // softmax row sums (atomic)

// ---------------------------------------------------------------------------
// helpers (family-safe PTX: ldmatrix / mma.sync / cp.async)
// ---------------------------------------------------------------------------
__device__ __forceinline__ uint32_t smem_u32(const void* p) {
    return (uint32_t)__cvta_generic_to_shared(p);
}
__device__ __forceinline__ void ldsm4(uint32_t* r, uint32_t addr) {
    asm volatile("ldmatrix.sync.aligned.m8n8.x4.shared.b16 {%0,%1,%2,%3}, [%4];"
                 : "=r"(r[0]), "=r"(r[1]), "=r"(r[2]), "=r"(r[3]) : "r"(addr));
}
__device__ __forceinline__ void mma16816h(uint32_t* c, const uint32_t* a, const uint32_t* b) {
    asm volatile(
        "mma.sync.aligned.m16n8k16.row.col.f16.f16.f16.f16 "
        "{%0,%1}, {%2,%3,%4,%5}, {%6,%7}, {%0,%1};"
        : "+r"(c[0]), "+r"(c[1])
        : "r"(a[0]), "r"(a[1]), "r"(a[2]), "r"(a[3]), "r"(b[0]), "r"(b[1]));
}
__device__ __forceinline__ void cp16(uint32_t dst, const void* src) {
    asm volatile("cp.async.cg.shared.global [%0], [%1], 16;" :: "r"(dst), "l"(src));
}
__device__ __forceinline__ void cp_commit() { asm volatile("cp.async.commit_group;" ::: "memory"); }
__device__ __forceinline__ void cp_wait1()  { asm volatile("cp.async.wait_group 1;" ::: "memory"); }

__device__ __forceinline__ float2 h2f2(uint32_t u) {
    return __half22float2(*reinterpret_cast<__half2*>(&u));
}
__device__ __forceinline__ uint32_t f2h2(float a, float b) {
    __half2 h = __floats2half2_rn(a, b);
    return *reinterpret_cast<uint32_t*>(&h);
}

#define KT      32
#define STRIDE  40
#define TILE_B  (128 * STRIDE * 2)      // 10240 B per operand tile
#define STG_B   (2 * TILE_B)            // 20480 B per stage (A+B)
#define NSTAGE  2
#define GEMM_SMEM (NSTAGE * STG_B)      // 40960 B

// ---------------------------------------------------------------------------
// 2-stage 128x128 GEMM: acc += A[128,K] * B[128,K]^T (fp16 -> fp16 acc)
// ---------------------------------------------------------------------------
template <int LD>
__device__ __forceinline__ void copy_tile(const fp16* A, const fp16* B,
                                          uint32_t sA, uint32_t sB, int k0, int tid) {
    #pragma unroll
    for (int c = 0; c < 2; c++) {
        int id = tid + 256 * c;
        int row = id >> 2, col = (id & 3) * 8;
        uint32_t off = (uint32_t)(row * STRIDE + col) * 2;
        cp16(sA + off, A + (size_t)row * LD + k0 + col);
        cp16(sB + off, B + (size_t)row * LD + k0 + col);
    }
    cp_commit();
}

template <int T, int LD>
__device__ __forceinline__ void gemm_ms(const fp16* A, const fp16* B,
                                        char* smem, uint32_t acc[2][8][2], int tid) {
    int lane = tid & 31, wid = tid >> 5;
    int wm = wid & 3, wn = wid >> 2;
    uint32_t base = smem_u32(smem);

    copy_tile<LD>(A, B, base, base + TILE_B, 0, tid);

    int ar = lane & 15, ak = (lane >> 4) * 8;
    uint32_t aoff = (uint32_t)((wm * 32 + ar) * STRIDE + ak) * 2;
    uint32_t boff = (uint32_t)((wn * 64 + ar) * STRIDE + ak) * 2 + TILE_B;

    #pragma unroll
    for (int t = 0; t < T; t++) {
        if (t + 1 < T) {
            uint32_t sb = base + ((t + 1) & 1) * STG_B;
            copy_tile<LD>(A, B, sb, sb + TILE_B, (t + 1) * KT, tid);
        } else {
            cp_commit();         // dummy group so wait1 retires the real last tile
        }
        cp_wait1();              // pending = {t, t+1} -> tile t resident
        __syncthreads();

        uint32_t stg = base + (t & 1) * STG_B;
        #pragma unroll
        for (int kk = 0; kk < 2; kk++) {
            uint32_t af[2][4];
            #pragma unroll
            for (int mt = 0; mt < 2; mt++)
                ldsm4(af[mt], stg + aoff + (uint32_t)(mt * 16 * STRIDE + kk * 16) * 2);
            #pragma unroll
            for (int np = 0; np < 4; np++) {
                uint32_t r[4];
                ldsm4(r, stg + boff + (uint32_t)(np * 16 * STRIDE + kk * 16) * 2);
                uint32_t b0[2] = {r[0], r[2]};
                uint32_t b1[2] = {r[1], r[3]};
                #pragma unroll
                for (int mt = 0; mt < 2; mt++) {
                    mma16816h(acc[mt][np * 2],     af[mt], b0);
                    mma16816h(acc[mt][np * 2 + 1], af[mt], b1);
                }
            }
        }
        __syncthreads();   // buffer t drained before copy at iter t+1 overwrites it
    }
}

// ---------------------------------------------------------------------------
// 128x64 GEMM (pv): 3-stage, warp tile 32x32, unroll-4 mainloop
// ---------------------------------------------------------------------------
#define TILE_B64  (64 * STRIDE * 2)          // 5120 B
#define STG_B64   (TILE_B + TILE_B64)        // 15360 B per stage
#define NST64     3
#define GEMM_SMEM64 (NST64 * STG_B64)        // 46080 B -> 4 CTAs/SM

template <int LD>
__device__ __forceinline__ void copy_tile64(const fp16* A, const fp16* B,
                                            uint32_t sA, uint32_t sB, int k0, int tid) {
    #pragma unroll
    for (int c = 0; c < 2; c++) {
        int id = tid + 256 * c;
        int row = id >> 2, col = (id & 3) * 8;
        cp16(sA + (uint32_t)(row * STRIDE + col) * 2, A + (size_t)row * LD + k0 + col);
    }
    {
        int row = tid >> 2, col = (tid & 3) * 8;   // 256 chunks = 64 rows
        cp16(sB + (uint32_t)(row * STRIDE + col) * 2, B + (size_t)row * LD + k0 + col);
    }
    cp_commit();
}

template <int T, int LD>
__device__ __forceinline__ void gemm_ms64(const fp16* A, const fp16* B,
                                          char* smem, uint32_t acc[2][4][2], int tid) {
    int lane = tid & 31, wid = tid >> 5;
    int wm = wid & 3, wn = wid >> 2;
    uint32_t base = smem_u32(smem);

    #pragma unroll
    for (int s = 0; s < NST64 - 1; s++)
        copy_tile64<LD>(A, B, base + s * STG_B64, base + s * STG_B64 + TILE_B, s * KT, tid);

    int ar = lane & 15, ak = (lane >> 4) * 8;
    uint32_t aoff = (uint32_t)((wm * 32 + ar) * STRIDE + ak) * 2;
    uint32_t boff = (uint32_t)((wn * 32 + ar) * STRIDE + ak) * 2 + TILE_B;

    #pragma unroll 4
    for (int t = 0; t < T; t++) {
        cp_wait1();
        __syncthreads();
        int nxt = t + NST64 - 1;
        if (nxt < T) {
            uint32_t sb = base + (nxt % NST64) * STG_B64;
            copy_tile64<LD>(A, B, sb, sb + TILE_B, nxt * KT, tid);
        } else {
            cp_commit();
        }
        uint32_t stg = base + (t % NST64) * STG_B64;

        #pragma unroll
        for (int kk = 0; kk < 2; kk++) {
            uint32_t af[2][4];
            #pragma unroll
            for (int mt = 0; mt < 2; mt++)
                ldsm4(af[mt], stg + aoff + (uint32_t)(mt * 16 * STRIDE + kk * 16) * 2);
            #pragma unroll
            for (int np = 0; np < 2; np++) {
                uint32_t r[4];
                ldsm4(r, stg + boff + (uint32_t)(np * 16 * STRIDE + kk * 16) * 2);
                uint32_t b0[2] = {r[0], r[2]};
                uint32_t b1[2] = {r[1], r[3]};
                #pragma unroll
                for (int mt = 0; mt < 2; mt++) {
                    mma16816h(acc[mt][np * 2],     af[mt], b0);
                    mma16816h(acc[mt][np * 2 + 1], af[mt], b1);
                }
            }
        }
    }
}

// ---------------------------------------------------------------------------
// 1a. GroupNorm stats (0..511) + weight fp32->fp16 (512..575) + rowsum zero (576..639)
// ---------------------------------------------------------------------------
__global__ __launch_bounds__(256) void gn_stats_kernel(const float* __restrict__ x,
                                                       const float* __restrict__ Wq,
                                                       const float* __restrict__ Wk,
                                                       const float* __restrict__ Wv) {
    int bx = blockIdx.x;
    if (bx >= 576) {
        g_rowsum[(bx - 576) * 256 + threadIdx.x] = 0.f;
        return;
    }
    if (bx >= 512) {
        int i = (bx - 512) * 256 + threadIdx.x;
        float4 a; uint2 u;
        a = reinterpret_cast<const float4*>(Wq)[i];
        u.x = f2h2(a.x, a.y); u.y = f2h2(a.z, a.w);
        reinterpret_cast<uint2*>(g_wq)[i] = u;
        a = reinterpret_cast<const float4*>(Wk)[i];
        u.x = f2h2(a.x, a.y); u.y = f2h2(a.z, a.w);
        reinterpret_cast<uint2*>(g_wk)[i] = u;
        a = reinterpret_cast<const float4*>(Wv)[i];
        u.x = f2h2(a.x, a.y); u.y = f2h2(a.z, a.w);
        reinterpret_cast<uint2*>(g_wv)[i] = u;
        return;
    }
    int s = bx & 7, bg = bx >> 3;
    const float* xp = x + (size_t)bg * GC * N_ + (size_t)s * 8192;
    float sum = 0.f, ss = 0.f;
    #pragma unroll
    for (int i = 0; i < 8; i++) {
        float4 v = reinterpret_cast<const float4*>(xp)[threadIdx.x + i * 256];
        sum += v.x + v.y + v.z + v.w;
        ss  += v.x * v.x + v.y * v.y + v.z * v.z + v.w * v.w;
    }
    __shared__ float sh1[256], sh2[256];
    sh1[threadIdx.x] = sum; sh2[threadIdx.x] = ss;
    __syncthreads();
    for (int o = 128; o > 0; o >>= 1) {
        if (threadIdx.x < o) {
            sh1[threadIdx.x] += sh1[threadIdx.x + o];
            sh2[threadIdx.x] += sh2[threadIdx.x + o];
        }
        __syncthreads();
    }
    if (threadIdx.x == 0) {
        g_red[bg][s][0] = sh1[0];
        g_red[bg][s][1] = sh2[0];
    }
}

// ---------------------------------------------------------------------------
// 1b. GroupNorm apply + transpose: x[b][c][n] -> hT[b][n][c] fp16
// ---------------------------------------------------------------------------
__global__ __launch_bounds__(256) void gn_apply_kernel(const float* __restrict__ x,
                                                       const float* __restrict__ gamma,
                                                       const float* __restrict__ beta) {
    int ns = blockIdx.x, g = blockIdx.y, b = blockIdx.z;
    int bg = b * NG + g;
    float sum = 0.f, ss = 0.f;
    #pragma unroll
    for (int i = 0; i < 8; i++) { sum += g_red[bg][i][0]; ss += g_red[bg][i][1]; }
    const float inv_n = 1.0f / (GC * N_);
    float mean = sum * inv_n;
    float var  = ss * inv_n - mean * mean;
    float rstd = rsqrtf(var + 1e-5f);

    const float* xp = x + (size_t)bg * GC * N_;
    fp16* out = g_hT + (size_t)b * N_ * C_ + g * GC;
    __shared__ float tile[32 * 65];
    int tid = threadIdx.x;
    int nbase = ns * 128;
    for (int n0 = nbase; n0 < nbase + 128; n0 += 32) {
        for (int e = tid; e < GC * 32; e += 256) {
            int c = e >> 5, n = e & 31;
            float v = (xp[(size_t)c * N_ + n0 + n] - mean) * rstd;
            v = v * __ldg(&gamma[g * GC + c]) + __ldg(&beta[g * GC + c]);
            tile[n * 65 + c] = v;
        }
        __syncthreads();
        {
            int n = tid >> 3, u = tid & 7;
            uint32_t pk[4];
            #pragma unroll
            for (int j = 0; j < 4; j++)
                pk[j] = f2h2(tile[n * 65 + u * 8 + 2 * j], tile[n * 65 + u * 8 + 2 * j + 1]);
            *reinterpret_cast<uint4*>(out + (size_t)(n0 + n) * C_ + u * 8) =
                *reinterpret_cast<uint4*>(pk);
        }
        __syncthreads();
    }
}

// ---------------------------------------------------------------------------
// 2a. QK: q = (hT @ Wq^T + bq) / 16,  k = hT @ Wk^T + bk   (512 CTAs)
// ---------------------------------------------------------------------------
__global__ __launch_bounds__(256, 3) void qk_kernel(const float* __restrict__ bq,
                                                    const float* __restrict__ bk) {
    extern __shared__ __align__(16) char dsm[];
    int tid = threadIdx.x;
    int mi = blockIdx.z & 1, b = blockIdx.z >> 1;
    int n0 = blockIdx.x * 128, m0 = blockIdx.y * 128;
    const fp16* A  = g_hT + (size_t)b * N_ * C_ + (size_t)m0 * C_;
    const fp16* Bm = (mi == 0 ? g_wq : g_wk) + (size_t)n0 * C_;
    uint32_t acc[2][8][2] = {};
    gemm_ms<C_ / KT, C_>(A, Bm, dsm, acc, tid);

    int lane = tid & 31, wid = tid >> 5;
    int wm = wid & 3, wn = wid >> 2;
    int quad = lane >> 2, qt = lane & 3;
    const float* bias = (mi == 0) ? bq : bk;

    fp16* out = ((mi == 0) ? g_q : g_k) + (size_t)b * N_ * C_;
    float scale = (mi == 0) ? 0.0625f : 1.0f;
    #pragma unroll
    for (int mt = 0; mt < 2; mt++) {
        int r0 = m0 + wm * 32 + mt * 16 + quad;
        #pragma unroll
        for (int nt = 0; nt < 8; nt++) {
            int d = n0 + wn * 64 + nt * 8 + qt * 2;
            float b0 = __ldg(&bias[d]), b1 = __ldg(&bias[d + 1]);
            float2 c01 = h2f2(acc[mt][nt][0]);
            float2 c23 = h2f2(acc[mt][nt][1]);
            uint32_t h0 = f2h2((c01.x + b0) * scale, (c01.y + b1) * scale);
            uint32_t h1 = f2h2((c23.x + b0) * scale, (c23.y + b1) * scale);
            *reinterpret_cast<uint32_t*>(out + (size_t)r0 * C_ + d) = h0;
            *reinterpret_cast<uint32_t*>(out + (size_t)(r0 + 8) * C_ + d) = h1;
        }
    }
}

// ---------------------------------------------------------------------------
// 2b. V: Vt[b][d][m] = (hT @ Wv^T + bv)^T   (256 CTAs, runs concurrent w/ score)
// ---------------------------------------------------------------------------
__global__ __launch_bounds__(256, 3) void v_kernel(const float* __restrict__ bv) {
    extern __shared__ __align__(16) char dsm[];
    int tid = threadIdx.x;
    int b = blockIdx.z;
    int n0 = blockIdx.x * 128, m0 = blockIdx.y * 128;
    const fp16* A  = g_hT + (size_t)b * N_ * C_ + (size_t)m0 * C_;
    const fp16* Bm = g_wv + (size_t)n0 * C_;
    uint32_t acc[2][8][2] = {};
    gemm_ms<C_ / KT, C_>(A, Bm, dsm, acc, tid);

    int lane = tid & 31, wid = tid >> 5;
    int wm = wid & 3, wn = wid >> 2;
    int quad = lane >> 2, qt = lane & 3;

    fp16* st = reinterpret_cast<fp16*>(dsm);   // [128 d][stride 136] = 34816 B
    __syncthreads();
    #pragma unroll
    for (int mt = 0; mt < 2; mt++) {
        int ml = wm * 32 + mt * 16 + quad;
        #pragma unroll
        for (int nt = 0; nt < 8; nt++) {
            int dl = wn * 64 + nt * 8 + qt * 2;
            float b0 = __ldg(&bv[n0 + dl]), b1 = __ldg(&bv[n0 + dl + 1]);
            float2 c01 = h2f2(acc[mt][nt][0]);
            float2 c23 = h2f2(acc[mt][nt][1]);
            st[dl * 136 + ml]           = __float2half_rn(c01.x + b0);
            st[(dl + 1) * 136 + ml]     = __float2half_rn(c01.y + b1);
            st[dl * 136 + ml + 8]       = __float2half_rn(c23.x + b0);
            st[(dl + 1) * 136 + ml + 8] = __float2half_rn(c23.y + b1);
        }
    }
    __syncthreads();
    fp16* outv = g_vt + (size_t)b * C_ * N_;
    #pragma unroll
    for (int c = 0; c < 8; c++) {
        int id = tid + 256 * c;
        int d = id >> 4, ch = (id & 15) * 8;
        *reinterpret_cast<uint4*>(outv + (size_t)(n0 + d) * N_ + m0 + ch) =
            *reinterpret_cast<uint4*>(st + d * 136 + ch);
    }
}

// ---------------------------------------------------------------------------
// 3. Scores as plain GEMM + exp epilogue (deferred normalization)
// ---------------------------------------------------------------------------
__global__ __launch_bounds__(256, 3) void score_kernel() {
    extern __shared__ __align__(16) char dsm[];
    int tid = threadIdx.x;
    int b = blockIdx.z;
    int n0 = blockIdx.x * 128, m0 = blockIdx.y * 128;
    const fp16* A  = g_q + (size_t)b * N_ * C_ + (size_t)m0 * C_;
    const fp16* Bm = g_k + (size_t)b * N_ * C_ + (size_t)n0 * C_;
    uint32_t acc[2][8][2] = {};
    gemm_ms<C_ / KT, C_>(A, Bm, dsm, acc, tid);

    int lane = tid & 31, wid = tid >> 5;
    int wm = wid & 3, wn = wid >> 2;
    int quad = lane >> 2, qt = lane & 3;

    fp16* P = g_p + (size_t)b * N_ * N_;
    float* rsum = g_rowsum + (size_t)b * N_;
    #pragma unroll
    for (int mt = 0; mt < 2; mt++) {
        int r0 = m0 + wm * 32 + mt * 16 + quad;
        float rs0 = 0.f, rs1 = 0.f;
        #pragma unroll
        for (int nt = 0; nt < 8; nt++) {
            int cc = n0 + wn * 64 + nt * 8 + qt * 2;
            float2 a01 = h2f2(acc[mt][nt][0]);
            float2 a23 = h2f2(acc[mt][nt][1]);
            float e0 = __expf(a01.x), e1 = __expf(a01.y);
            float e2 = __expf(a23.x), e3 = __expf(a23.y);
            rs0 += e0 + e1;
            rs1 += e2 + e3;
            *reinterpret_cast<uint32_t*>(P + (size_t)r0 * N_ + cc)       = f2h2(e0, e1);
            *reinterpret_cast<uint32_t*>(P + (size_t)(r0 + 8) * N_ + cc) = f2h2(e2, e3);
        }
        rs0 += __shfl_xor_sync(0xffffffffu, rs0, 1);
        rs0 += __shfl_xor_sync(0xffffffffu, rs0, 2);
        rs1 += __shfl_xor_sync(0xffffffffu, rs1, 1);
        rs1 += __shfl_xor_sync(0xffffffffu, rs1, 2);
        if (qt == 0) {
            atomicAdd(&rsum[r0], rs0);
            atomicAdd(&rsum[r0 + 8], rs1);
        }
    }
}

// ---------------------------------------------------------------------------
// 4. PV as O^T, tile 128 channels x 64 tokens (512 CTAs, 4 CTAs/SM)
// ---------------------------------------------------------------------------
__global__ __launch_bounds__(256, 4) void pv_kernel(const float* __restrict__ x,
                                                    float* __restrict__ outp) {
    extern __shared__ __align__(16) char dsm[];
    int tid = threadIdx.x;
    int b = blockIdx.z;
    int n0 = blockIdx.x * 64;    // token tile (64)
    int m0 = blockIdx.y * 128;   // channel tile (128)
    const fp16* A  = g_vt + (size_t)b * C_ * N_ + (size_t)m0 * N_;
    const fp16* Bm = g_p  + (size_t)b * N_ * N_ + (size_t)n0 * N_;
    uint32_t acc[2][4][2] = {};
    gemm_ms64<N_ / KT, N_>(A, Bm, dsm, acc, tid);

    int lane = tid & 31, wid = tid >> 5;
    int wm = wid & 3, wn = wid >> 2;
    int quad = lane >> 2, qt = lane & 3;
    const float* rsum = g_rowsum + (size_t)b * N_;
    #pragma unroll
    for (int mt = 0; mt < 2; mt++) {
        int cg = m0 + wm * 32 + mt * 16 + quad;
        #pragma unroll
        for (int nt = 0; nt < 4; nt++) {
            int ng = n0 + wn * 32 + nt * 8 + qt * 2;
            float inv0 = 1.0f / __ldg(&rsum[ng]);
            float inv1 = 1.0f / __ldg(&rsum[ng + 1]);
            size_t base = ((size_t)b * C_ + cg) * N_ + ng;
            float2 c01 = h2f2(acc[mt][nt][0]);
            float2 c23 = h2f2(acc[mt][nt][1]);
            float2 xv = *reinterpret_cast<const float2*>(x + base);
            *reinterpret_cast<float2*>(outp + base) =
                make_float2(c01.x * inv0 + xv.x, c01.y * inv1 + xv.y);
            size_t base8 = base + (size_t)8 * N_;
            float2 xv8 = *reinterpret_cast<const float2*>(x + base8);
            *reinterpret_cast<float2*>(outp + base8) =
                make_float2(c23.x * inv0 + xv8.x, c23.y * inv1 + xv8.y);
        }
    }
}

// ---------------------------------------------------------------------------
extern "C" void kernel_launch(void* const* d_in, const int* in_sizes, int n_in,
                              void* d_out, int out_size) {
    const float* x     = (const float*)d_in[0];
    const float* Wq    = (const float*)d_in[1];
    const float* bq    = (const float*)d_in[2];
    const float* Wk    = (const float*)d_in[3];
    const float* bk    = (const float*)d_in[4];
    const float* Wv    = (const float*)d_in[5];
    const float* bv    = (const float*)d_in[6];
    const float* gamma = (const float*)d_in[7];
    const float* beta  = (const float*)d_in[8];
    float* out = (float*)d_out;

    static cudaStream_t s2 = nullptr;
    static cudaEvent_t evA = nullptr, evB = nullptr;
    if (s2 == nullptr) {
        cudaStreamCreateWithFlags(&s2, cudaStreamNonBlocking);
        cudaEventCreateWithFlags(&evA, cudaEventDisableTiming);
        cudaEventCreateWithFlags(&evB, cudaEventDisableTiming);
        cudaFuncSetAttribute(qk_kernel, cudaFuncAttributeMaxDynamicSharedMemorySize, GEMM_SMEM);
        cudaFuncSetAttribute(v_kernel, cudaFuncAttributeMaxDynamicSharedMemorySize, GEMM_SMEM);
        cudaFuncSetAttribute(score_kernel, cudaFuncAttributeMaxDynamicSharedMemorySize, GEMM_SMEM);
        cudaFuncSetAttribute(pv_kernel, cudaFuncAttributeMaxDynamicSharedMemorySize, GEMM_SMEM64);
    }

    gn_stats_kernel<<<640, 256>>>(x, Wq, Wk, Wv);
    gn_apply_kernel<<<dim3(8, NG, B_), 256>>>(x, gamma, beta);
    qk_kernel<<<dim3(2, 8, 2 * B_), 256, GEMM_SMEM>>>(bq, bk);

    // Fork: V projection (needed only by pv) runs concurrently with score.
    cudaEventRecord(evA, 0);
    cudaStreamWaitEvent(s2, evA, 0);
    v_kernel<<<dim3(2, 8, B_), 256, GEMM_SMEM, s2>>>(bv);
    cudaEventRecord(evB, s2);

    score_kernel<<<dim3(8, 8, B_), 256, GEMM_SMEM>>>();

    // Join: pv needs both score (main stream) and v (s2).
    cudaStreamWaitEvent(0, evB, 0);
    pv_kernel<<<dim3(16, 2, B_), 256, GEMM_SMEM64>>>(x, out);
}